// round 14
// baseline (speedup 1.0000x reference)
#include <cuda_runtime.h>
#include <math.h>
#include <stdint.h>

// Problem constants
#define BB 16
#define NN 512
#define DD 768
#define HH 3
#define DHD 1536
#define DKH 512
#define NKEY 384
#define LCV 766
#define MTOT (BB*NN)          // 8192
#define NZCAP 32

// ---------------- scratch (device globals; no allocation allowed) ----------------
__device__ float g_denom [MTOT];
__device__ float g_Ax    [MTOT*DD];
__device__ float g_xw0   [MTOT*DD];
__device__ float g_out1  [MTOT*DD];
__device__ float g_Y     [3L*BB*NN*DD];
__device__ float g_conve [MTOT*LCV];
__device__ float g_x     [MTOT*DHD];
__device__ float g_q     [MTOT*DKH];
__device__ float g_k     [BB*NKEY*DKH];
__device__ float g_P     [(long)BB*NN*NN];
__device__ float g_out2  [MTOT*DD];
__device__ float g_h1    [MTOT*DD];
__device__ float g_thr   [BB];
__device__ int   g_nzc   [BB];
__device__ int   g_nzi   [BB*NZCAP];
__device__ int   g_nzj   [BB*NZCAP];

// pre-split weight buffers (fragment-order, hi/lo)
__device__ uint32_t g_W0h[6*48*2048],  g_W0l[6*48*2048];
__device__ uint32_t g_lch[6*48*2048],  g_lcl[6*48*2048];
__device__ uint32_t g_qwh[4*96*2048],  g_qwl[4*96*2048];
__device__ uint32_t g_kwh[4*96*2048],  g_kwl[4*96*2048];
__device__ uint32_t g_W1h[6*96*2048],  g_W1l[6*96*2048];
__device__ uint32_t g_f1h[6*48*2048],  g_f1l[6*48*2048];
__device__ uint32_t g_f2h[6*48*2048],  g_f2l[6*48*2048];
__device__ uint32_t g_wpAh[3*4*32*2048], g_wpAl[3*4*32*2048];

enum { EP_STORE=0, EP_BIASCOL=1, EP_GCN=3, EP_RELU=4, EP_GCN0=5 };

__device__ __forceinline__ void tf32split(float v, uint32_t& hb, uint32_t& lb) {
    asm("cvt.rna.tf32.f32 %0, %1;" : "=r"(hb) : "f"(v));
    float rem = v - __uint_as_float(hb);
    asm("cvt.rna.tf32.f32 %0, %1;" : "=r"(lb) : "f"(rem));
}

__device__ __forceinline__ void mma8(float* c, const uint32_t* a, const uint32_t* b) {
    asm volatile(
        "mma.sync.aligned.m16n8k8.row.col.f32.tf32.tf32.f32 "
        "{%0,%1,%2,%3}, {%4,%5,%6,%7}, {%8,%9}, {%0,%1,%2,%3};"
        : "+f"(c[0]), "+f"(c[1]), "+f"(c[2]), "+f"(c[3])
        : "r"(a[0]), "r"(a[1]), "r"(a[2]), "r"(a[3]), "r"(b[0]), "r"(b[1]));
}

__device__ __forceinline__ void cp16(uint32_t sm, const void* g) {
    asm volatile("cp.async.cg.shared.global [%0], [%1], 16;" :: "r"(sm), "l"(g));
}
#define CP_COMMIT() asm volatile("cp.async.commit_group;" ::: "memory")
#define CP_WAIT0()  asm volatile("cp.async.wait_group 0;" ::: "memory")

// ---------------- pre-split kernels ----------------
// B-fragment order: fi = (((kc<<4)+nt)*32 + ((nn<<2)|(kk&3)))*2 + (kk>>2)
__global__ void splitB_k(const float* __restrict__ src, uint32_t* __restrict__ H,
                         uint32_t* __restrict__ L, int N, int K, int ldb, int NT, int NC) {
    int idx = blockIdx.x * 256 + threadIdx.x;
    if (idx >= NT*NC*2048) return;
    int fi = idx & 2047, blk = idx >> 11;
    int c = blk % NC, tn = blk / NC;
    int e = fi & 1, t1 = fi >> 1;
    int lane = t1 & 31, t2 = t1 >> 5;
    int nt = t2 & 15, kc = t2 >> 4;
    int n = tn*128 + nt*8 + (lane >> 2);
    int k = c*16 + kc*8 + (lane & 3) + (e << 2);
    float v = (n < N && k < K) ? src[(long)n*ldb + k] : 0.f;
    uint32_t hb, lb; tf32split(v, hb, lb);
    H[idx] = hb; L[idx] = lb;
}

// A-fragment order for conv weights (wpack fused):
// fi = (((kc<<3)+mt)*32 + (((r&7)<<2)|(kk&3)))*4 + (((kk>>2)<<1)|(r>>3))
__global__ void splitWpA_k(const float* __restrict__ cvw, uint32_t* __restrict__ H,
                           uint32_t* __restrict__ L) {
    int idx = blockIdx.x * 256 + threadIdx.x;
    if (idx >= 3*4*32*2048) return;
    int fi = idx & 2047, blk = idx >> 11;
    int c = blk % 32, rest = blk / 32;
    int mt4 = rest % 4, t = rest / 4;
    int j = fi & 3, t1 = fi >> 2;
    int lane = t1 & 31, t2 = t1 >> 5;
    int mt = t2 & 7, kc = t2 >> 3;
    int r = (lane >> 2) | ((j & 1) << 3);
    int kk = (lane & 3) | ((j >> 1) << 2);
    int m = mt4*128 + mt*16 + r;
    int k = c*16 + kc*8 + kk;
    float v = cvw[((long)m*NN + k)*3 + t];   // wp[t][m][k] = cvw[m,k,t]
    uint32_t hb, lb; tf32split(v, hb, lb);
    H[idx] = hb; L[idx] = lb;
}

// ======================= tf32x3 tensor GEMM via mma.sync =======================
#define SMT_STAGE 8192
#define SMT_TOTAL (2*SMT_STAGE*4)

template<bool TB, bool APRE, bool BPRE, int EPI>
__global__ __launch_bounds__(256, 2)
void tmma_k(const float* __restrict__ A, const float* __restrict__ Bm, float* __restrict__ C,
            int M, int N, int K, int lda, int ldb, int ldc,
            long sAo, long sAi, long sBo, long sBi, long sCo, long sCi, int innerB,
            const float* __restrict__ bias, const float* __restrict__ denom,
            const float* __restrict__ addm, float scale,
            const uint32_t* __restrict__ aph, const uint32_t* __restrict__ apl,
            const uint32_t* __restrict__ bph, const uint32_t* __restrict__ bpl,
            int atiles)
{
    extern __shared__ uint32_t smu[];
    uint32_t smbase = (uint32_t)__cvta_generic_to_shared(smu);

    int tid = threadIdx.x;
    int wid = tid >> 5, lane = tid & 31;
    int wm = wid >> 2, wn = wid & 3;
    int z = blockIdx.z, zo = z / innerB, zi = z % innerB;
    A  += (long)zo*sAo + (long)zi*sAi;
    Bm += (long)zo*sBo + (long)zi*sBi;
    C  += (long)zo*sCo + (long)zi*sCi;
    int bm = blockIdx.y * 128, bn = blockIdx.x * 128;
    int nc = (K + 15) / 16;

    float acc[4][4][4];
    #pragma unroll
    for (int i = 0; i < 4; i++)
        #pragma unroll
        for (int j = 0; j < 4; j++)
            #pragma unroll
            for (int r = 0; r < 4; r++) acc[i][j][r] = 0.f;

    float av[8], bv[8];

    auto loadA = [&](int k0) {
        #pragma unroll
        for (int l = 0; l < 8; l++) {
            int idx = tid + l*256;
            int m = idx >> 4, k = idx & 15;
            int gr = bm + m, gk = k0 + k;
            av[l] = (gr < M && gk < K) ? A[(long)gr*lda + gk] : 0.f;
        }
    };
    auto loadB = [&](int k0) {
        #pragma unroll
        for (int l = 0; l < 8; l++) {
            int idx = tid + l*256;
            int n, k;
            if (TB) { n = idx >> 4;  k = idx & 15; }
            else    { k = idx >> 7;  n = idx & 127; }
            int gn = bn + n, gk = k0 + k;
            bv[l] = (gn < N && gk < K) ?
                (TB ? Bm[(long)gn*ldb + gk] : Bm[(long)gk*ldb + gn]) : 0.f;
        }
    };
    auto stageA = [&](uint32_t* buf) {
        uint32_t* AH = buf; uint32_t* AL = buf + 2048;
        #pragma unroll
        for (int l = 0; l < 8; l++) {
            int idx = tid + l*256;
            int m = idx >> 4, k = idx & 15;
            uint32_t hb, lb; tf32split(av[l], hb, lb);
            int kc = k >> 3, kk = k & 7, mt = m >> 4, r = m & 15;
            int fi = (((kc<<3) + mt)*32 + (((r&7)<<2) | (kk&3)))*4
                   + (((kk>>2)<<1) | (r>>3));
            AH[fi] = hb; AL[fi] = lb;
        }
    };
    auto stageB = [&](uint32_t* buf) {
        uint32_t* BH = buf + 4096; uint32_t* BL = buf + 6144;
        #pragma unroll
        for (int l = 0; l < 8; l++) {
            int idx = tid + l*256;
            int n, k;
            if (TB) { n = idx >> 4;  k = idx & 15; }
            else    { k = idx >> 7;  n = idx & 127; }
            uint32_t hb, lb; tf32split(bv[l], hb, lb);
            int kc = k >> 3, kk = k & 7, nt = n >> 3, nn = n & 7;
            int fi = (((kc<<4) + nt)*32 + ((nn<<2) | (kk&3)))*2 + (kk>>2);
            BH[fi] = hb; BL[fi] = lb;
        }
    };
    auto cpA = [&](int c, int bufw) {
        long blk = ((long)(zo*atiles + (bm>>7))*nc + c)*2048;
        const uint32_t* sh = aph + blk; const uint32_t* sl = apl + blk;
        #pragma unroll
        for (int l = 0; l < 2; l++) {
            int o = (tid + l*256)*4;
            cp16(smbase + (bufw + o)*4,        sh + o);
            cp16(smbase + (bufw + 2048 + o)*4, sl + o);
        }
    };
    auto cpB = [&](int c, int bufw) {
        long blk = ((long)(bn>>7)*nc + c)*2048;
        const uint32_t* sh = bph + blk; const uint32_t* sl = bpl + blk;
        #pragma unroll
        for (int l = 0; l < 2; l++) {
            int o = (tid + l*256)*4;
            cp16(smbase + (bufw + 4096 + o)*4, sh + o);
            cp16(smbase + (bufw + 6144 + o)*4, sl + o);
        }
    };
    auto compute = [&](const uint32_t* buf) {
        const uint32_t* AH = buf;        const uint32_t* AL = buf + 2048;
        const uint32_t* BH = buf + 4096; const uint32_t* BL = buf + 6144;
        #pragma unroll
        for (int kc = 0; kc < 2; kc++) {
            uint32_t bh[4][2], bl[4][2];
            #pragma unroll
            for (int nt = 0; nt < 4; nt++) {
                int bbase = (((kc<<4) + (wn*4 + nt))*32 + lane)*2;
                *(uint2*)bh[nt] = *(const uint2*)(BH + bbase);
                *(uint2*)bl[nt] = *(const uint2*)(BL + bbase);
            }
            #pragma unroll
            for (int mt = 0; mt < 4; mt++) {
                uint32_t ah[4], al[4];
                int abase = (((kc<<3) + (wm*4 + mt))*32 + lane)*4;
                *(uint4*)ah = *(const uint4*)(AH + abase);
                *(uint4*)al = *(const uint4*)(AL + abase);
                #pragma unroll
                for (int nt = 0; nt < 4; nt++) {
                    mma8(acc[mt][nt], ah, bh[nt]);
                    mma8(acc[mt][nt], ah, bl[nt]);
                    mma8(acc[mt][nt], al, bh[nt]);
                }
            }
        }
    };

    // prologue
    if (!APRE) loadA(0); else cpA(0, 0);
    if (!BPRE) loadB(0); else cpB(0, 0);
    if (APRE || BPRE) CP_COMMIT();

    for (int c = 0; c < nc; c++) {
        int bufw = (c & 1) * SMT_STAGE;
        uint32_t* buf = smu + bufw;
        if (!APRE) stageA(buf);
        if (!BPRE) stageB(buf);
        if (APRE || BPRE) CP_WAIT0();
        __syncthreads();
        if (c + 1 < nc) {
            int nbufw = ((c+1) & 1) * SMT_STAGE;
            if (!APRE) loadA((c+1)*16); else cpA(c+1, nbufw);
            if (!BPRE) loadB((c+1)*16); else cpB(c+1, nbufw);
            if (APRE || BPRE) CP_COMMIT();
        }
        compute(buf);
    }

    // epilogue
    int r0 = lane >> 2, c0 = 2*(lane & 3);
    #pragma unroll
    for (int mt = 0; mt < 4; mt++) {
        #pragma unroll
        for (int half = 0; half < 2; half++) {
            int gr = bm + wm*64 + mt*16 + r0 + half*8;
            if (gr >= M) continue;
            float dn = (EPI == EP_GCN) ? denom[gr] : 1.f;
            #pragma unroll
            for (int nt = 0; nt < 4; nt++) {
                #pragma unroll
                for (int e = 0; e < 2; e++) {
                    int gc = bn + wn*32 + nt*8 + c0 + e;
                    if (gc >= N) continue;
                    float v = acc[mt][nt][half*2 + e];
                    if (EPI == EP_STORE)        v *= scale;
                    else if (EPI == EP_BIASCOL) v += bias[gc];
                    else if (EPI == EP_GCN)     v = fmaxf((v + bias[gc]) / dn, 0.f)
                                                  + addm[(long)gr*ldc + gc];
                    else if (EPI == EP_RELU)    v = fmaxf(v, 0.f);
                    else if (EPI == EP_GCN0)    v = v + bias[gc] + fmaxf(bias[gc], 0.f);
                    C[(long)gr*ldc + gc] = v;
                }
            }
        }
    }
}

// ---------------- small kernels ----------------
__global__ void rowsum_adj_k(const float* __restrict__ a, float* __restrict__ d) {
    int row = blockIdx.x;
    const float* p = a + (long)row * NN;
    float s = 0.f;
    for (int j = threadIdx.x; j < NN; j += 128) s += p[j];
    __shared__ float sm[128];
    sm[threadIdx.x] = s; __syncthreads();
    for (int o = 64; o > 0; o >>= 1) { if (threadIdx.x < o) sm[threadIdx.x] += sm[threadIdx.x+o]; __syncthreads(); }
    if (threadIdx.x == 0) d[row] = sm[0] + 1.f;
}

__global__ void copy_inputs_k(const float* __restrict__ in, float* __restrict__ x) {
    long i = (long)blockIdx.x * 256 + threadIdx.x;
    if (i < (long)MTOT * DD) {
        long r = i / DD, c = i % DD;
        x[r * DHD + c] = in[i];
    }
}

__global__ void combine_k(const float* __restrict__ Y, const float* __restrict__ cvb,
                          float* __restrict__ conve) {
    long i = (long)blockIdx.x * 256 + threadIdx.x;
    if (i < (long)BB*NN*LCV) {
        int  l = (int)(i % LCV);
        int  o = (int)((i / LCV) % NN);
        int  b = (int)(i / ((long)NN*LCV));
        long base = ((long)b*NN + o)*DD + l;
        const long ts = (long)BB*NN*DD;
        float v = Y[base] + Y[ts + base + 1] + Y[2*ts + base + 2];
        conve[i] = fmaxf(v + cvb[o], 0.f);
    }
}

__global__ __launch_bounds__(128) void softmax_k(float* __restrict__ P) {
    int row = blockIdx.x;
    float* p = P + (long)row * NN;
    int t = threadIdx.x;
    __shared__ float sm[128];
    float m = -1e30f;
    for (int j = t; j < NKEY; j += 128) m = fmaxf(m, p[j]);
    sm[t] = m; __syncthreads();
    for (int o = 64; o > 0; o >>= 1) { if (t < o) sm[t] = fmaxf(sm[t], sm[t+o]); __syncthreads(); }
    float M = sm[0]; __syncthreads();
    float s = 0.f;
    for (int j = t; j < NKEY; j += 128) { float e = expf(p[j] - M); p[j] = e; s += e; }
    sm[t] = s; __syncthreads();
    for (int o = 64; o > 0; o >>= 1) { if (t < o) sm[t] += sm[t+o]; __syncthreads(); }
    float S = sm[0]; __syncthreads();
    for (int j = t; j < NKEY; j += 128) p[j] = p[j] / S;
    for (int j = NKEY + t; j < NN; j += 128) p[j] = 0.f;
}

__global__ __launch_bounds__(256) void top2_k(const float* __restrict__ P,
                                              float* __restrict__ thr) {
    int b = blockIdx.x;
    const float* p = P + (long)b * NN * NN;
    float m1 = -1e30f, m2 = -1e30f;
    for (long i = threadIdx.x; i < (long)NN*NN; i += 256) {
        float v = p[i];
        if (v > m1) { m2 = m1; m1 = v; }
        else if (v > m2) m2 = v;
    }
    __shared__ float s1[256], s2[256];
    s1[threadIdx.x] = m1; s2[threadIdx.x] = m2; __syncthreads();
    if (threadIdx.x == 0) {
        float M1 = -1e30f, M2 = -1e30f;
        for (int i = 0; i < 256; i++) {
            float a = s1[i], a2 = s2[i];
            if (a > M1) { M2 = fmaxf(M1, a2); M1 = a; }
            else if (a > M2) M2 = a;
        }
        thr[b] = M2;
    }
}

__global__ __launch_bounds__(256) void extract_k(const float* __restrict__ P,
                                                 const float* __restrict__ thr,
                                                 int* __restrict__ nzc,
                                                 int* __restrict__ nzi,
                                                 int* __restrict__ nzj) {
    int b = blockIdx.x;
    const float* p = P + (long)b * NN * NN;
    float th = thr[b];
    __shared__ int cnt;
    __shared__ int li[NZCAP], lj[NZCAP];
    if (threadIdx.x == 0) cnt = 0;
    __syncthreads();
    for (long idx = threadIdx.x; idx < (long)NN*NN; idx += 256) {
        if (p[idx] >= th) {
            int s = atomicAdd(&cnt, 1);
            if (s < NZCAP) { li[s] = (int)(idx / NN); lj[s] = (int)(idx % NN); }
        }
    }
    __syncthreads();
    if (threadIdx.x == 0) {
        int n = cnt < NZCAP ? cnt : NZCAP;
        for (int a = 1; a < n; a++) {
            int ii = li[a], jj = lj[a];
            int w = a - 1;
            while (w >= 0 && (li[w] > ii || (li[w] == ii && lj[w] > jj))) {
                li[w+1] = li[w]; lj[w+1] = lj[w]; w--;
            }
            li[w+1] = ii; lj[w+1] = jj;
        }
        nzc[b] = n;
        for (int a = 0; a < n; a++) { nzi[b*NZCAP + a] = li[a]; nzj[b*NZCAP + a] = lj[a]; }
    }
}

__global__ __launch_bounds__(256) void fixup_k(const int* __restrict__ nzc,
                                               const int* __restrict__ nzi,
                                               const int* __restrict__ nzj,
                                               const float* __restrict__ x,
                                               const float* __restrict__ W1w,
                                               const float* __restrict__ W1b,
                                               float* __restrict__ out2) {
    int b = blockIdx.x, t = threadIdx.x;
    int n = nzc[b];
    __shared__ int ei[NZCAP], ej[NZCAP];
    __shared__ float axrow[DHD];
    if (t < n) { ei[t] = nzi[b*NZCAP + t]; ej[t] = nzj[b*NZCAP + t]; }
    __syncthreads();
    for (int e = 0; e < n; e++) {
        int i = ei[e];
        bool first = true;
        for (int e2 = 0; e2 < e; e2++) if (ei[e2] == i) first = false;
        if (!first) continue;
        for (int k = t; k < DHD; k += 256) axrow[k] = 0.f;
        __syncthreads();
        float den = 1.f;
        for (int e2 = e; e2 < n; e2++) {
            if (ei[e2] != i) continue;
            int j = ej[e2];
            float bji = 0.f;
            for (int e3 = 0; e3 < n; e3++) if (ei[e3] == j && ej[e3] == i) bji = 1.f;
            float a = (i == j) ? 1.f : (1.f + bji);
            den += a;
            const float* xr = x + ((long)b*NN + j)*DHD;
            for (int k = t; k < DHD; k += 256) axrow[k] += a * xr[k];
            __syncthreads();
        }
        float* orow = out2 + ((long)b*NN + i)*DD;
        for (int c = t; c < DD; c += 256) {
            const float* wrow = W1w + (long)c*DHD;
            float dot = 0.f;
            for (int k = 0; k < DHD; k++) dot += axrow[k] * wrow[k];
            float bc = W1b[c];
            float xw1v = orow[c] - fmaxf(bc, 0.f);
            orow[c] = fmaxf((dot + bc) / den, 0.f) + xw1v;
        }
        __syncthreads();
    }
}

// ---------------- launch ----------------
static inline dim3 ggrid(int Ncols, int Mrows, int batch) {
    return dim3((Ncols + 127) / 128, (Mrows + 127) / 128, batch);
}

extern "C" void kernel_launch(void* const* d_in, const int* in_sizes, int n_in,
                              void* d_out, int out_size) {
    const float* adj    = (const float*)d_in[0];
    const float* inputs = (const float*)d_in[1];
    const float* W0w = (const float*)d_in[3];  const float* W0b = (const float*)d_in[4];
    const float* W1w = (const float*)d_in[5];  const float* W1b = (const float*)d_in[6];
    const float* cvw = (const float*)d_in[7];  const float* cvb = (const float*)d_in[8];
    const float* lcw = (const float*)d_in[9];  const float* lcb = (const float*)d_in[10];
    const float* f1w = (const float*)d_in[11]; const float* f2w = (const float*)d_in[12];
    const float* qw  = (const float*)d_in[13]; const float* qb  = (const float*)d_in[14];
    const float* kw  = (const float*)d_in[15]; const float* kb  = (const float*)d_in[16];
    float* out = (float*)d_out;

    float *p_denom, *p_Ax, *p_xw0, *p_out1, *p_Y, *p_conve, *p_x, *p_q, *p_k, *p_P;
    float *p_out2, *p_h1, *p_thr;
    int *p_nzc, *p_nzi, *p_nzj;
    uint32_t *W0h,*W0l,*lch,*lcl,*qwh,*qwl,*kwh,*kwl,*W1h,*W1l,*f1h,*f1l,*f2h,*f2l,*wpAh,*wpAl;
    cudaGetSymbolAddress((void**)&p_denom,  g_denom);
    cudaGetSymbolAddress((void**)&p_Ax,     g_Ax);
    cudaGetSymbolAddress((void**)&p_xw0,    g_xw0);
    cudaGetSymbolAddress((void**)&p_out1,   g_out1);
    cudaGetSymbolAddress((void**)&p_Y,      g_Y);
    cudaGetSymbolAddress((void**)&p_conve,  g_conve);
    cudaGetSymbolAddress((void**)&p_x,      g_x);
    cudaGetSymbolAddress((void**)&p_q,      g_q);
    cudaGetSymbolAddress((void**)&p_k,      g_k);
    cudaGetSymbolAddress((void**)&p_P,      g_P);
    cudaGetSymbolAddress((void**)&p_out2,   g_out2);
    cudaGetSymbolAddress((void**)&p_h1,     g_h1);
    cudaGetSymbolAddress((void**)&p_thr,    g_thr);
    cudaGetSymbolAddress((void**)&p_nzc,    g_nzc);
    cudaGetSymbolAddress((void**)&p_nzi,    g_nzi);
    cudaGetSymbolAddress((void**)&p_nzj,    g_nzj);
    cudaGetSymbolAddress((void**)&W0h, g_W0h);  cudaGetSymbolAddress((void**)&W0l, g_W0l);
    cudaGetSymbolAddress((void**)&lch, g_lch);  cudaGetSymbolAddress((void**)&lcl, g_lcl);
    cudaGetSymbolAddress((void**)&qwh, g_qwh);  cudaGetSymbolAddress((void**)&qwl, g_qwl);
    cudaGetSymbolAddress((void**)&kwh, g_kwh);  cudaGetSymbolAddress((void**)&kwl, g_kwl);
    cudaGetSymbolAddress((void**)&W1h, g_W1h);  cudaGetSymbolAddress((void**)&W1l, g_W1l);
    cudaGetSymbolAddress((void**)&f1h, g_f1h);  cudaGetSymbolAddress((void**)&f1l, g_f1l);
    cudaGetSymbolAddress((void**)&f2h, g_f2h);  cudaGetSymbolAddress((void**)&f2l, g_f2l);
    cudaGetSymbolAddress((void**)&wpAh, g_wpAh); cudaGetSymbolAddress((void**)&wpAl, g_wpAl);

    #define SETSM(F) cudaFuncSetAttribute(F, cudaFuncAttributeMaxDynamicSharedMemorySize, SMT_TOTAL)
    SETSM((tmma_k<false, false, false, EP_STORE>));
    SETSM((tmma_k<false, true,  false, EP_STORE>));
    SETSM((tmma_k<true,  false, true,  EP_STORE>));
    SETSM((tmma_k<true,  false, false, EP_STORE>));
    SETSM((tmma_k<true,  false, true,  EP_BIASCOL>));
    SETSM((tmma_k<true,  false, true,  EP_GCN>));
    SETSM((tmma_k<true,  false, true,  EP_RELU>));
    SETSM((tmma_k<true,  false, true,  EP_GCN0>));

    const long NND = (long)NN*DD, NNN = (long)NN*NN, NNH = (long)NN*DHD;
    const uint32_t* NU = nullptr;

    // 0) pre-split weights (fragment order, hi/lo)
    splitB_k<<<(6*48*2048)/256, 256>>>(W0w, W0h, W0l, DD, DD, DD, 6, 48);
    splitB_k<<<(6*48*2048)/256, 256>>>(lcw, lch, lcl, DD, LCV, LCV, 6, 48);
    splitB_k<<<(4*96*2048)/256, 256>>>(qw,  qwh, qwl, DKH, DHD, DHD, 4, 96);
    splitB_k<<<(4*96*2048)/256, 256>>>(kw,  kwh, kwl, DKH, DHD, DHD, 4, 96);
    splitB_k<<<(6*96*2048)/256, 256>>>(W1w, W1h, W1l, DD, DHD, DHD, 6, 96);
    splitB_k<<<(6*48*2048)/256, 256>>>(f1w, f1h, f1l, DD, DD, DD, 6, 48);
    splitB_k<<<(6*48*2048)/256, 256>>>(f2w, f2h, f2l, DD, DD, DD, 6, 48);
    splitWpA_k<<<(3*4*32*2048)/256, 256>>>(cvw, wpAh, wpAl);

    // 1) denom
    rowsum_adj_k<<<MTOT, 128>>>(adj, p_denom);

    // 2) Ax = adj @ inputs
    tmma_k<false, false, false, EP_STORE><<<ggrid(DD, NN, BB), 256, SMT_TOTAL>>>(
        adj, inputs, p_Ax, NN, DD, NN, NN, DD, DD,
        NNN, 0, NND, 0, NND, 0, 1, nullptr, nullptr, nullptr, 1.f, NU,NU,NU,NU, 0);

    // 3) xw0 = inputs @ W0^T + b   [B pre-split]
    tmma_k<true, false, true, EP_BIASCOL><<<ggrid(DD, MTOT, 1), 256, SMT_TOTAL>>>(
        inputs, W0w, p_xw0, MTOT, DD, DD, DD, DD, DD,
        0,0,0,0,0,0, 1, W0b, nullptr, nullptr, 1.f, NU,NU, W0h,W0l, 0);

    // 4) out1 = relu((Ax@W0^T + b)/denom) + xw0   [B pre-split]
    tmma_k<true, false, true, EP_GCN><<<ggrid(DD, MTOT, 1), 256, SMT_TOTAL>>>(
        p_Ax, W0w, p_out1, MTOT, DD, DD, DD, DD, DD,
        0,0,0,0,0,0, 1, W0b, p_denom, p_xw0, 1.f, NU,NU, W0h,W0l, 0);

    // 5b) Y[t][b] = W_t @ out1[b]  (batched 48)  [A pre-split]
    tmma_k<false, true, false, EP_STORE><<<ggrid(DD, NN, 3*BB), 256, SMT_TOTAL>>>(
        nullptr, p_out1, p_Y, NN, DD, NN, NN, DD, DD,
        0, 0, 0, NND, (long)BB*NN*DD, NND, BB,
        nullptr, nullptr, nullptr, 1.f, wpAh, wpAl, NU,NU, 4);

    // 5c) combine + relu + bias
    combine_k<<<(int)(((long)BB*NN*LCV + 255)/256), 256>>>(p_Y, cvb, p_conve);

    // 7) x[:, :768] = inputs
    copy_inputs_k<<<(int)(((long)MTOT*DD + 255)/256), 256>>>(inputs, p_x);

    // 8) x[:, 768:] = conve @ linearc^T + b   [B pre-split]
    tmma_k<true, false, true, EP_BIASCOL><<<ggrid(DD, MTOT, 1), 256, SMT_TOTAL>>>(
        p_conve, lcw, p_x + DD, MTOT, DD, LCV, LCV, LCV, DHD,
        0,0,0,0,0,0, 1, lcb, nullptr, nullptr, 1.f, NU,NU, lch,lcl, 0);

    // 9) q projection (head 0)   [B pre-split]
    tmma_k<true, false, true, EP_BIASCOL><<<ggrid(DKH, MTOT, 1), 256, SMT_TOTAL>>>(
        p_x, qw, p_q, MTOT, DKH, DHD, DHD, DHD, DKH,
        0,0,0,0,0,0, 1, qb, nullptr, nullptr, 1.f, NU,NU, qwh,qwl, 0);
    // 10) k projection (head 0, keys<384, batched)   [B pre-split]
    tmma_k<true, false, true, EP_BIASCOL><<<ggrid(DKH, NKEY, BB), 256, SMT_TOTAL>>>(
        p_x, kw, p_k, NKEY, DKH, DHD, DHD, DHD, DKH,
        NNH, 0, 0, 0, (long)NKEY*DKH, 0, 1, kb, nullptr, nullptr, 1.f, NU,NU, kwh,kwl, 0);

    // 11) scores = q k^T / sqrt(512) (batched 16)
    {
        float scl = 1.0f / sqrtf(512.0f);
        tmma_k<true, false, false, EP_STORE><<<ggrid(NKEY, NN, BB), 256, SMT_TOTAL>>>(
            p_q, p_k, p_P, NN, NKEY, DKH, DKH, DKH, NN,
            (long)NN*DKH, 0, (long)NKEY*DKH, 0, NNN, 0, 1,
            nullptr, nullptr, nullptr, scl, NU,NU,NU,NU, 0);
    }

    // 12) softmax (head 0)
    softmax_k<<<BB*NN, 128>>>(p_P);
    // 14) top-2 threshold
    top2_k<<<BB, 256>>>(p_P, p_thr);
    // 15) sparse bbin extraction
    extract_k<<<BB, 256>>>(p_P, p_thr, p_nzc, p_nzi, p_nzj);

    // 17) out2 = relu(b) + (x @ W1^T + b)   [B pre-split]
    tmma_k<true, false, true, EP_GCN0><<<ggrid(DD, MTOT, 1), 256, SMT_TOTAL>>>(
        p_x, W1w, p_out2, MTOT, DD, DHD, DHD, DHD, DD,
        0,0,0,0,0,0, 1, W1b, nullptr, nullptr, 1.f, NU,NU, W1h,W1l, 0);

    // 18) sparse fixup
    fixup_k<<<BB, 256>>>(p_nzc, p_nzi, p_nzj, p_x, W1w, W1b, p_out2);

    // 19) h1 = relu(out2 @ fc1^T)   [B pre-split]
    tmma_k<true, false, true, EP_RELU><<<ggrid(DD, MTOT, 1), 256, SMT_TOTAL>>>(
        p_out2, f1w, p_h1, MTOT, DD, DD, DD, DD, DD,
        0,0,0,0,0,0, 1, nullptr, nullptr, nullptr, 1.f, NU,NU, f1h,f1l, 0);

    // 20) out = h1 @ fc2^T   [B pre-split]
    tmma_k<true, false, true, EP_STORE><<<ggrid(DD, MTOT, 1), 256, SMT_TOTAL>>>(
        p_h1, f2w, out, MTOT, DD, DD, DD, DD, DD,
        0,0,0,0,0,0, 1, nullptr, nullptr, nullptr, 1.f, NU,NU, f2h,f2l, 0);
}

// round 15
// speedup vs baseline: 1.4929x; 1.4929x over previous
#include <cuda_runtime.h>
#include <math.h>
#include <stdint.h>

// Problem constants
#define BB 16
#define NN 512
#define DD 768
#define HH 3
#define DHD 1536
#define DKH 512
#define NKEY 384
#define LCV 766
#define MTOT (BB*NN)          // 8192
#define NZCAP 32

// ---------------- scratch (device globals; no allocation allowed) ----------------
__device__ float g_denom [MTOT];
__device__ float g_Ax    [MTOT*DD];
__device__ float g_xw0   [MTOT*DD];
__device__ float g_out1  [MTOT*DD];
__device__ float g_wpack [3*NN*NN];
__device__ float g_Y     [3L*BB*NN*DD];
__device__ float g_conve [MTOT*LCV];
__device__ float g_x     [MTOT*DHD];
__device__ float g_q     [MTOT*DKH];
__device__ float g_k     [BB*NKEY*DKH];
__device__ float g_P     [(long)BB*NN*NN];
__device__ float g_out2  [MTOT*DD];
__device__ float g_h1    [MTOT*DD];
__device__ float g_thr   [BB];
__device__ int   g_nzc   [BB];
__device__ int   g_nzi   [BB*NZCAP];
__device__ int   g_nzj   [BB*NZCAP];

// pre-split weight buffers (fragment-order, hi/lo) — layout proven correct in R14
__device__ uint32_t g_W0h[6*48*2048],  g_W0l[6*48*2048];
__device__ uint32_t g_lch[6*48*2048],  g_lcl[6*48*2048];
__device__ uint32_t g_qwh[4*96*2048],  g_qwl[4*96*2048];
__device__ uint32_t g_kwh[4*96*2048],  g_kwl[4*96*2048];
__device__ uint32_t g_W1h[6*96*2048],  g_W1l[6*96*2048];
__device__ uint32_t g_f1h[6*48*2048],  g_f1l[6*48*2048];
__device__ uint32_t g_f2h[6*48*2048],  g_f2l[6*48*2048];

enum { EP_STORE=0, EP_BIASCOL=1, EP_GCN=3, EP_RELU=4, EP_GCN0=5 };

__device__ __forceinline__ void tf32split(float v, uint32_t& hb, uint32_t& lb) {
    asm("cvt.rna.tf32.f32 %0, %1;" : "=r"(hb) : "f"(v));
    float rem = v - __uint_as_float(hb);
    asm("cvt.rna.tf32.f32 %0, %1;" : "=r"(lb) : "f"(rem));
}

__device__ __forceinline__ void mma8(float* c, const uint32_t* a, const uint32_t* b) {
    asm volatile(
        "mma.sync.aligned.m16n8k8.row.col.f32.tf32.tf32.f32 "
        "{%0,%1,%2,%3}, {%4,%5,%6,%7}, {%8,%9}, {%0,%1,%2,%3};"
        : "+f"(c[0]), "+f"(c[1]), "+f"(c[2]), "+f"(c[3])
        : "r"(a[0]), "r"(a[1]), "r"(a[2]), "r"(a[3]), "r"(b[0]), "r"(b[1]));
}

// ---------------- pre-split kernel (B fragment order; verified in R14) ----------
__global__ void splitB_k(const float* __restrict__ src, uint32_t* __restrict__ H,
                         uint32_t* __restrict__ L, int N, int K, int ldb, int NT, int NC) {
    int idx = blockIdx.x * 256 + threadIdx.x;
    if (idx >= NT*NC*2048) return;
    int fi = idx & 2047, blk = idx >> 11;
    int c = blk % NC, tn = blk / NC;
    int e = fi & 1, t1 = fi >> 1;
    int lane = t1 & 31, t2 = t1 >> 5;
    int nt = t2 & 15, kc = t2 >> 4;
    int n = tn*128 + nt*8 + (lane >> 2);
    int k = c*16 + kc*8 + (lane & 3) + (e << 2);
    float v = (n < N && k < K) ? src[(long)n*ldb + k] : 0.f;
    uint32_t hb, lb; tf32split(v, hb, lb);
    H[idx] = hb; L[idx] = lb;
}

// ======================= tf32x3 tensor GEMM via mma.sync =======================
// R15 = R13 pipeline + (BPRE) vectorized LDG prefetch from pre-split buffers.
#define SMT_STAGE 8192
#define SMT_TOTAL (2*SMT_STAGE*4)

template<bool TB, bool BPRE, int EPI>
__global__ __launch_bounds__(256, 2)
void tmma_k(const float* __restrict__ A, const float* __restrict__ Bm, float* __restrict__ C,
            int M, int N, int K, int lda, int ldb, int ldc,
            long sAo, long sAi, long sBo, long sBi, long sCo, long sCi, int innerB,
            const float* __restrict__ bias, const float* __restrict__ denom,
            const float* __restrict__ addm, float scale,
            const uint32_t* __restrict__ bph, const uint32_t* __restrict__ bpl)
{
    extern __shared__ uint32_t smu[];

    int tid = threadIdx.x;
    int wid = tid >> 5, lane = tid & 31;
    int wm = wid >> 2, wn = wid & 3;
    int z = blockIdx.z, zo = z / innerB, zi = z % innerB;
    A  += (long)zo*sAo + (long)zi*sAi;
    Bm += (long)zo*sBo + (long)zi*sBi;
    C  += (long)zo*sCo + (long)zi*sCi;
    int bm = blockIdx.y * 128, bn = blockIdx.x * 128;
    int nc = (K + 15) / 16;

    float acc[4][4][4];
    #pragma unroll
    for (int i = 0; i < 4; i++)
        #pragma unroll
        for (int j = 0; j < 4; j++)
            #pragma unroll
            for (int r = 0; r < 4; r++) acc[i][j][r] = 0.f;

    float av[8], bv[8];
    uint4 pbh0, pbh1, pbl0, pbl1;

    auto loadA = [&](int k0) {
        #pragma unroll
        for (int l = 0; l < 8; l++) {
            int idx = tid + l*256;
            int m = idx >> 4, k = idx & 15;
            int gr = bm + m, gk = k0 + k;
            av[l] = (gr < M && gk < K) ? A[(long)gr*lda + gk] : 0.f;
        }
    };
    auto loadB = [&](int c) {
        if (BPRE) {
            long blk = ((long)(bn>>7)*nc + c)*2048;
            const uint4* sh = (const uint4*)(bph + blk);
            const uint4* sl = (const uint4*)(bpl + blk);
            pbh0 = sh[tid]; pbh1 = sh[tid+256];
            pbl0 = sl[tid]; pbl1 = sl[tid+256];
        } else {
            int k0 = c*16;
            #pragma unroll
            for (int l = 0; l < 8; l++) {
                int idx = tid + l*256;
                int n, k;
                if (TB) { n = idx >> 4;  k = idx & 15; }
                else    { k = idx >> 7;  n = idx & 127; }
                int gn = bn + n, gk = k0 + k;
                bv[l] = (gn < N && gk < K) ?
                    (TB ? Bm[(long)gn*ldb + gk] : Bm[(long)gk*ldb + gn]) : 0.f;
            }
        }
    };
    auto stageA = [&](uint32_t* buf) {
        uint32_t* AH = buf; uint32_t* AL = buf + 2048;
        #pragma unroll
        for (int l = 0; l < 8; l++) {
            int idx = tid + l*256;
            int m = idx >> 4, k = idx & 15;
            uint32_t hb, lb; tf32split(av[l], hb, lb);
            int kc = k >> 3, kk = k & 7, mt = m >> 4, r = m & 15;
            int fi = (((kc<<3) + mt)*32 + (((r&7)<<2) | (kk&3)))*4
                   + (((kk>>2)<<1) | (r>>3));
            AH[fi] = hb; AL[fi] = lb;
        }
    };
    auto stageB = [&](uint32_t* buf) {
        if (BPRE) {
            uint4* BH = (uint4*)(buf + 4096); uint4* BL = (uint4*)(buf + 6144);
            BH[tid] = pbh0; BH[tid+256] = pbh1;
            BL[tid] = pbl0; BL[tid+256] = pbl1;
        } else {
            uint32_t* BH = buf + 4096; uint32_t* BL = buf + 6144;
            #pragma unroll
            for (int l = 0; l < 8; l++) {
                int idx = tid + l*256;
                int n, k;
                if (TB) { n = idx >> 4;  k = idx & 15; }
                else    { k = idx >> 7;  n = idx & 127; }
                uint32_t hb, lb; tf32split(bv[l], hb, lb);
                int kc = k >> 3, kk = k & 7, nt = n >> 3, nn = n & 7;
                int fi = (((kc<<4) + nt)*32 + ((nn<<2) | (kk&3)))*2 + (kk>>2);
                BH[fi] = hb; BL[fi] = lb;
            }
        }
    };
    auto compute = [&](const uint32_t* buf) {
        const uint32_t* AH = buf;        const uint32_t* AL = buf + 2048;
        const uint32_t* BH = buf + 4096; const uint32_t* BL = buf + 6144;
        #pragma unroll
        for (int kc = 0; kc < 2; kc++) {
            uint32_t bh[4][2], bl[4][2];
            #pragma unroll
            for (int nt = 0; nt < 4; nt++) {
                int bbase = (((kc<<4) + (wn*4 + nt))*32 + lane)*2;
                *(uint2*)bh[nt] = *(const uint2*)(BH + bbase);
                *(uint2*)bl[nt] = *(const uint2*)(BL + bbase);
            }
            #pragma unroll
            for (int mt = 0; mt < 4; mt++) {
                uint32_t ah[4], al[4];
                int abase = (((kc<<3) + (wm*4 + mt))*32 + lane)*4;
                *(uint4*)ah = *(const uint4*)(AH + abase);
                *(uint4*)al = *(const uint4*)(AL + abase);
                #pragma unroll
                for (int nt = 0; nt < 4; nt++) {
                    mma8(acc[mt][nt], ah, bh[nt]);
                    mma8(acc[mt][nt], ah, bl[nt]);
                    mma8(acc[mt][nt], al, bh[nt]);
                }
            }
        }
    };

    loadA(0); loadB(0);
    for (int c = 0; c < nc; c++) {
        uint32_t* buf = smu + (c & 1) * SMT_STAGE;
        stageA(buf);
        stageB(buf);
        __syncthreads();
        if (c + 1 < nc) { loadA((c+1)*16); loadB(c+1); }
        compute(buf);
    }

    // epilogue
    int r0 = lane >> 2, c0 = 2*(lane & 3);
    #pragma unroll
    for (int mt = 0; mt < 4; mt++) {
        #pragma unroll
        for (int half = 0; half < 2; half++) {
            int gr = bm + wm*64 + mt*16 + r0 + half*8;
            if (gr >= M) continue;
            float dn = (EPI == EP_GCN) ? denom[gr] : 1.f;
            #pragma unroll
            for (int nt = 0; nt < 4; nt++) {
                #pragma unroll
                for (int e = 0; e < 2; e++) {
                    int gc = bn + wn*32 + nt*8 + c0 + e;
                    if (gc >= N) continue;
                    float v = acc[mt][nt][half*2 + e];
                    if (EPI == EP_STORE)        v *= scale;
                    else if (EPI == EP_BIASCOL) v += bias[gc];
                    else if (EPI == EP_GCN)     v = fmaxf((v + bias[gc]) / dn, 0.f)
                                                  + addm[(long)gr*ldc + gc];
                    else if (EPI == EP_RELU)    v = fmaxf(v, 0.f);
                    else if (EPI == EP_GCN0)    v = v + bias[gc] + fmaxf(bias[gc], 0.f);
                    C[(long)gr*ldc + gc] = v;
                }
            }
        }
    }
}

// ---------------- small kernels ----------------
__global__ void rowsum_adj_k(const float* __restrict__ a, float* __restrict__ d) {
    int row = blockIdx.x;
    const float* p = a + (long)row * NN;
    float s = 0.f;
    for (int j = threadIdx.x; j < NN; j += 128) s += p[j];
    __shared__ float sm[128];
    sm[threadIdx.x] = s; __syncthreads();
    for (int o = 64; o > 0; o >>= 1) { if (threadIdx.x < o) sm[threadIdx.x] += sm[threadIdx.x+o]; __syncthreads(); }
    if (threadIdx.x == 0) d[row] = sm[0] + 1.f;
}

__global__ void copy_inputs_k(const float* __restrict__ in, float* __restrict__ x) {
    long i = (long)blockIdx.x * 256 + threadIdx.x;
    if (i < (long)MTOT * DD) {
        long r = i / DD, c = i % DD;
        x[r * DHD + c] = in[i];
    }
}

__global__ void wpack_k(const float* __restrict__ cvw, float* __restrict__ wp) {
    int i = blockIdx.x * 256 + threadIdx.x;
    if (i < 3*NN*NN) {
        int t = i / (NN*NN);
        int o = (i / NN) % NN;
        int c = i % NN;
        wp[i] = cvw[(long)o*NN*3 + c*3 + t];
    }
}

__global__ void combine_k(const float* __restrict__ Y, const float* __restrict__ cvb,
                          float* __restrict__ conve) {
    long i = (long)blockIdx.x * 256 + threadIdx.x;
    if (i < (long)BB*NN*LCV) {
        int  l = (int)(i % LCV);
        int  o = (int)((i / LCV) % NN);
        int  b = (int)(i / ((long)NN*LCV));
        long base = ((long)b*NN + o)*DD + l;
        const long ts = (long)BB*NN*DD;
        float v = Y[base] + Y[ts + base + 1] + Y[2*ts + base + 2];
        conve[i] = fmaxf(v + cvb[o], 0.f);
    }
}

__global__ __launch_bounds__(128) void softmax_k(float* __restrict__ P) {
    int row = blockIdx.x;
    float* p = P + (long)row * NN;
    int t = threadIdx.x;
    __shared__ float sm[128];
    float m = -1e30f;
    for (int j = t; j < NKEY; j += 128) m = fmaxf(m, p[j]);
    sm[t] = m; __syncthreads();
    for (int o = 64; o > 0; o >>= 1) { if (t < o) sm[t] = fmaxf(sm[t], sm[t+o]); __syncthreads(); }
    float M = sm[0]; __syncthreads();
    float s = 0.f;
    for (int j = t; j < NKEY; j += 128) { float e = expf(p[j] - M); p[j] = e; s += e; }
    sm[t] = s; __syncthreads();
    for (int o = 64; o > 0; o >>= 1) { if (t < o) sm[t] += sm[t+o]; __syncthreads(); }
    float S = sm[0]; __syncthreads();
    for (int j = t; j < NKEY; j += 128) p[j] = p[j] / S;
    for (int j = NKEY + t; j < NN; j += 128) p[j] = 0.f;
}

__global__ __launch_bounds__(256) void top2_k(const float* __restrict__ P,
                                              float* __restrict__ thr) {
    int b = blockIdx.x;
    const float* p = P + (long)b * NN * NN;
    float m1 = -1e30f, m2 = -1e30f;
    for (long i = threadIdx.x; i < (long)NN*NN; i += 256) {
        float v = p[i];
        if (v > m1) { m2 = m1; m1 = v; }
        else if (v > m2) m2 = v;
    }
    __shared__ float s1[256], s2[256];
    s1[threadIdx.x] = m1; s2[threadIdx.x] = m2; __syncthreads();
    if (threadIdx.x == 0) {
        float M1 = -1e30f, M2 = -1e30f;
        for (int i = 0; i < 256; i++) {
            float a = s1[i], a2 = s2[i];
            if (a > M1) { M2 = fmaxf(M1, a2); M1 = a; }
            else if (a > M2) M2 = a;
        }
        thr[b] = M2;
    }
}

__global__ __launch_bounds__(256) void extract_k(const float* __restrict__ P,
                                                 const float* __restrict__ thr,
                                                 int* __restrict__ nzc,
                                                 int* __restrict__ nzi,
                                                 int* __restrict__ nzj) {
    int b = blockIdx.x;
    const float* p = P + (long)b * NN * NN;
    float th = thr[b];
    __shared__ int cnt;
    __shared__ int li[NZCAP], lj[NZCAP];
    if (threadIdx.x == 0) cnt = 0;
    __syncthreads();
    for (long idx = threadIdx.x; idx < (long)NN*NN; idx += 256) {
        if (p[idx] >= th) {
            int s = atomicAdd(&cnt, 1);
            if (s < NZCAP) { li[s] = (int)(idx / NN); lj[s] = (int)(idx % NN); }
        }
    }
    __syncthreads();
    if (threadIdx.x == 0) {
        int n = cnt < NZCAP ? cnt : NZCAP;
        for (int a = 1; a < n; a++) {
            int ii = li[a], jj = lj[a];
            int w = a - 1;
            while (w >= 0 && (li[w] > ii || (li[w] == ii && lj[w] > jj))) {
                li[w+1] = li[w]; lj[w+1] = lj[w]; w--;
            }
            li[w+1] = ii; lj[w+1] = jj;
        }
        nzc[b] = n;
        for (int a = 0; a < n; a++) { nzi[b*NZCAP + a] = li[a]; nzj[b*NZCAP + a] = lj[a]; }
    }
}

__global__ __launch_bounds__(256) void fixup_k(const int* __restrict__ nzc,
                                               const int* __restrict__ nzi,
                                               const int* __restrict__ nzj,
                                               const float* __restrict__ x,
                                               const float* __restrict__ W1w,
                                               const float* __restrict__ W1b,
                                               float* __restrict__ out2) {
    int b = blockIdx.x, t = threadIdx.x;
    int n = nzc[b];
    __shared__ int ei[NZCAP], ej[NZCAP];
    __shared__ float axrow[DHD];
    if (t < n) { ei[t] = nzi[b*NZCAP + t]; ej[t] = nzj[b*NZCAP + t]; }
    __syncthreads();
    for (int e = 0; e < n; e++) {
        int i = ei[e];
        bool first = true;
        for (int e2 = 0; e2 < e; e2++) if (ei[e2] == i) first = false;
        if (!first) continue;
        for (int k = t; k < DHD; k += 256) axrow[k] = 0.f;
        __syncthreads();
        float den = 1.f;
        for (int e2 = e; e2 < n; e2++) {
            if (ei[e2] != i) continue;
            int j = ej[e2];
            float bji = 0.f;
            for (int e3 = 0; e3 < n; e3++) if (ei[e3] == j && ej[e3] == i) bji = 1.f;
            float a = (i == j) ? 1.f : (1.f + bji);
            den += a;
            const float* xr = x + ((long)b*NN + j)*DHD;
            for (int k = t; k < DHD; k += 256) axrow[k] += a * xr[k];
            __syncthreads();
        }
        float* orow = out2 + ((long)b*NN + i)*DD;
        for (int c = t; c < DD; c += 256) {
            const float* wrow = W1w + (long)c*DHD;
            float dot = 0.f;
            for (int k = 0; k < DHD; k++) dot += axrow[k] * wrow[k];
            float bc = W1b[c];
            float xw1v = orow[c] - fmaxf(bc, 0.f);
            orow[c] = fmaxf((dot + bc) / den, 0.f) + xw1v;
        }
        __syncthreads();
    }
}

// ---------------- launch ----------------
static inline dim3 ggrid(int Ncols, int Mrows, int batch) {
    return dim3((Ncols + 127) / 128, (Mrows + 127) / 128, batch);
}

extern "C" void kernel_launch(void* const* d_in, const int* in_sizes, int n_in,
                              void* d_out, int out_size) {
    const float* adj    = (const float*)d_in[0];
    const float* inputs = (const float*)d_in[1];
    const float* W0w = (const float*)d_in[3];  const float* W0b = (const float*)d_in[4];
    const float* W1w = (const float*)d_in[5];  const float* W1b = (const float*)d_in[6];
    const float* cvw = (const float*)d_in[7];  const float* cvb = (const float*)d_in[8];
    const float* lcw = (const float*)d_in[9];  const float* lcb = (const float*)d_in[10];
    const float* f1w = (const float*)d_in[11]; const float* f2w = (const float*)d_in[12];
    const float* qw  = (const float*)d_in[13]; const float* qb  = (const float*)d_in[14];
    const float* kw  = (const float*)d_in[15]; const float* kb  = (const float*)d_in[16];
    float* out = (float*)d_out;

    float *p_denom, *p_Ax, *p_xw0, *p_out1, *p_wp, *p_Y, *p_conve, *p_x, *p_q, *p_k, *p_P;
    float *p_out2, *p_h1, *p_thr;
    int *p_nzc, *p_nzi, *p_nzj;
    uint32_t *W0h,*W0l,*lch,*lcl,*qwh,*qwl,*kwh,*kwl,*W1h,*W1l,*f1h,*f1l,*f2h,*f2l;
    cudaGetSymbolAddress((void**)&p_denom,  g_denom);
    cudaGetSymbolAddress((void**)&p_Ax,     g_Ax);
    cudaGetSymbolAddress((void**)&p_xw0,    g_xw0);
    cudaGetSymbolAddress((void**)&p_out1,   g_out1);
    cudaGetSymbolAddress((void**)&p_wp,     g_wpack);
    cudaGetSymbolAddress((void**)&p_Y,      g_Y);
    cudaGetSymbolAddress((void**)&p_conve,  g_conve);
    cudaGetSymbolAddress((void**)&p_x,      g_x);
    cudaGetSymbolAddress((void**)&p_q,      g_q);
    cudaGetSymbolAddress((void**)&p_k,      g_k);
    cudaGetSymbolAddress((void**)&p_P,      g_P);
    cudaGetSymbolAddress((void**)&p_out2,   g_out2);
    cudaGetSymbolAddress((void**)&p_h1,     g_h1);
    cudaGetSymbolAddress((void**)&p_thr,    g_thr);
    cudaGetSymbolAddress((void**)&p_nzc,    g_nzc);
    cudaGetSymbolAddress((void**)&p_nzi,    g_nzi);
    cudaGetSymbolAddress((void**)&p_nzj,    g_nzj);
    cudaGetSymbolAddress((void**)&W0h, g_W0h);  cudaGetSymbolAddress((void**)&W0l, g_W0l);
    cudaGetSymbolAddress((void**)&lch, g_lch);  cudaGetSymbolAddress((void**)&lcl, g_lcl);
    cudaGetSymbolAddress((void**)&qwh, g_qwh);  cudaGetSymbolAddress((void**)&qwl, g_qwl);
    cudaGetSymbolAddress((void**)&kwh, g_kwh);  cudaGetSymbolAddress((void**)&kwl, g_kwl);
    cudaGetSymbolAddress((void**)&W1h, g_W1h);  cudaGetSymbolAddress((void**)&W1l, g_W1l);
    cudaGetSymbolAddress((void**)&f1h, g_f1h);  cudaGetSymbolAddress((void**)&f1l, g_f1l);
    cudaGetSymbolAddress((void**)&f2h, g_f2h);  cudaGetSymbolAddress((void**)&f2l, g_f2l);

    #define SETSM(F) cudaFuncSetAttribute(F, cudaFuncAttributeMaxDynamicSharedMemorySize, SMT_TOTAL)
    SETSM((tmma_k<false, false, EP_STORE>));
    SETSM((tmma_k<true,  false, EP_STORE>));
    SETSM((tmma_k<true,  true,  EP_STORE>));
    SETSM((tmma_k<true,  true,  EP_BIASCOL>));
    SETSM((tmma_k<true,  true,  EP_GCN>));
    SETSM((tmma_k<true,  true,  EP_RELU>));
    SETSM((tmma_k<true,  true,  EP_GCN0>));

    const long NND = (long)NN*DD, NNN = (long)NN*NN, NNH = (long)NN*DHD;
    const uint32_t* NU = nullptr;

    // 0) pre-split weights (fragment order, hi/lo)
    splitB_k<<<(6*48*2048)/256, 256>>>(W0w, W0h, W0l, DD, DD, DD, 6, 48);
    splitB_k<<<(6*48*2048)/256, 256>>>(lcw, lch, lcl, DD, LCV, LCV, 6, 48);
    splitB_k<<<(4*96*2048)/256, 256>>>(qw,  qwh, qwl, DKH, DHD, DHD, 4, 96);
    splitB_k<<<(4*96*2048)/256, 256>>>(kw,  kwh, kwl, DKH, DHD, DHD, 4, 96);
    splitB_k<<<(6*96*2048)/256, 256>>>(W1w, W1h, W1l, DD, DHD, DHD, 6, 96);
    splitB_k<<<(6*48*2048)/256, 256>>>(f1w, f1h, f1l, DD, DD, DD, 6, 48);
    splitB_k<<<(6*48*2048)/256, 256>>>(f2w, f2h, f2l, DD, DD, DD, 6, 48);

    // 1) denom
    rowsum_adj_k<<<MTOT, 128>>>(adj, p_denom);

    // 2) Ax = adj @ inputs
    tmma_k<false, false, EP_STORE><<<ggrid(DD, NN, BB), 256, SMT_TOTAL>>>(
        adj, inputs, p_Ax, NN, DD, NN, NN, DD, DD,
        NNN, 0, NND, 0, NND, 0, 1, nullptr, nullptr, nullptr, 1.f, NU, NU);

    // 3) xw0 = inputs @ W0^T + b   [B pre-split, LDG.128 prefetch]
    tmma_k<true, true, EP_BIASCOL><<<ggrid(DD, MTOT, 1), 256, SMT_TOTAL>>>(
        inputs, W0w, p_xw0, MTOT, DD, DD, DD, DD, DD,
        0,0,0,0,0,0, 1, W0b, nullptr, nullptr, 1.f, W0h, W0l);

    // 4) out1 = relu((Ax@W0^T + b)/denom) + xw0   [B pre-split]
    tmma_k<true, true, EP_GCN><<<ggrid(DD, MTOT, 1), 256, SMT_TOTAL>>>(
        p_Ax, W0w, p_out1, MTOT, DD, DD, DD, DD, DD,
        0,0,0,0,0,0, 1, W0b, p_denom, p_xw0, 1.f, W0h, W0l);

    // 5a) conv weight repack
    wpack_k<<<(3*NN*NN + 255)/256, 256>>>(cvw, p_wp);
    // 5b) Y[t][b] = W_t @ out1[b]  (batched 48)
    tmma_k<false, false, EP_STORE><<<ggrid(DD, NN, 3*BB), 256, SMT_TOTAL>>>(
        p_wp, p_out1, p_Y, NN, DD, NN, NN, DD, DD,
        NNN, 0, 0, NND, (long)BB*NN*DD, NND, BB,
        nullptr, nullptr, nullptr, 1.f, NU, NU);
    // 5c) combine + relu + bias
    combine_k<<<(int)(((long)BB*NN*LCV + 255)/256), 256>>>(p_Y, cvb, p_conve);

    // 7) x[:, :768] = inputs
    copy_inputs_k<<<(int)(((long)MTOT*DD + 255)/256), 256>>>(inputs, p_x);

    // 8) x[:, 768:] = conve @ linearc^T + b   [B pre-split]
    tmma_k<true, true, EP_BIASCOL><<<ggrid(DD, MTOT, 1), 256, SMT_TOTAL>>>(
        p_conve, lcw, p_x + DD, MTOT, DD, LCV, LCV, LCV, DHD,
        0,0,0,0,0,0, 1, lcb, nullptr, nullptr, 1.f, lch, lcl);

    // 9) q projection (head 0)   [B pre-split]
    tmma_k<true, true, EP_BIASCOL><<<ggrid(DKH, MTOT, 1), 256, SMT_TOTAL>>>(
        p_x, qw, p_q, MTOT, DKH, DHD, DHD, DHD, DKH,
        0,0,0,0,0,0, 1, qb, nullptr, nullptr, 1.f, qwh, qwl);
    // 10) k projection (head 0, keys<384, batched)   [B pre-split]
    tmma_k<true, true, EP_BIASCOL><<<ggrid(DKH, NKEY, BB), 256, SMT_TOTAL>>>(
        p_x, kw, p_k, NKEY, DKH, DHD, DHD, DHD, DKH,
        NNH, 0, 0, 0, (long)NKEY*DKH, 0, 1, kb, nullptr, nullptr, 1.f, kwh, kwl);

    // 11) scores = q k^T / sqrt(512) (batched 16)
    {
        float scl = 1.0f / sqrtf(512.0f);
        tmma_k<true, false, EP_STORE><<<ggrid(NKEY, NN, BB), 256, SMT_TOTAL>>>(
            p_q, p_k, p_P, NN, NKEY, DKH, DKH, DKH, NN,
            (long)NN*DKH, 0, (long)NKEY*DKH, 0, NNN, 0, 1,
            nullptr, nullptr, nullptr, scl, NU, NU);
    }

    // 12) softmax (head 0)
    softmax_k<<<BB*NN, 128>>>(p_P);
    // 14) top-2 threshold
    top2_k<<<BB, 256>>>(p_P, p_thr);
    // 15) sparse bbin extraction
    extract_k<<<BB, 256>>>(p_P, p_thr, p_nzc, p_nzi, p_nzj);

    // 17) out2 = relu(b) + (x @ W1^T + b)   [B pre-split]
    tmma_k<true, true, EP_GCN0><<<ggrid(DD, MTOT, 1), 256, SMT_TOTAL>>>(
        p_x, W1w, p_out2, MTOT, DD, DHD, DHD, DHD, DD,
        0,0,0,0,0,0, 1, W1b, nullptr, nullptr, 1.f, W1h, W1l);

    // 18) sparse fixup
    fixup_k<<<BB, 256>>>(p_nzc, p_nzi, p_nzj, p_x, W1w, W1b, p_out2);

    // 19) h1 = relu(out2 @ fc1^T)   [B pre-split]
    tmma_k<true, true, EP_RELU><<<ggrid(DD, MTOT, 1), 256, SMT_TOTAL>>>(
        p_out2, f1w, p_h1, MTOT, DD, DD, DD, DD, DD,
        0,0,0,0,0,0, 1, nullptr, nullptr, nullptr, 1.f, f1h, f1l);

    // 20) out = h1 @ fc2^T   [B pre-split]
    tmma_k<true, true, EP_STORE><<<ggrid(DD, MTOT, 1), 256, SMT_TOTAL>>>(
        p_h1, f2w, out, MTOT, DD, DD, DD, DD, DD,
        0,0,0,0,0,0, 1, nullptr, nullptr, nullptr, 1.f, f2h, f2l);
}

// round 16
// speedup vs baseline: 2.0593x; 1.3794x over previous
#include <cuda_runtime.h>
#include <cuda_bf16.h>
#include <math.h>
#include <stdint.h>

// Problem constants
#define BB 16
#define NN 512
#define DD 768
#define HH 3
#define DHD 1536
#define DKH 512
#define NKEY 384
#define LCV 766
#define MTOT (BB*NN)          // 8192
#define NZCAP 32

// ---------------- scratch (device globals; no allocation allowed) ----------------
__device__ float g_denom [MTOT];
__device__ float g_Ax    [MTOT*DD];
__device__ float g_xw0   [MTOT*DD];
__device__ float g_out1  [MTOT*DD];
__device__ float g_wpack [3*NN*NN];
__device__ float g_Y     [3L*BB*NN*DD];
__device__ float g_conve [MTOT*LCV];
__device__ float g_x     [MTOT*DHD];
__device__ float g_q     [MTOT*DKH];
__device__ float g_k     [BB*NKEY*DKH];
__device__ float g_P     [(long)BB*NN*NN];
__device__ float g_out2  [MTOT*DD];
__device__ float g_h1    [MTOT*DD];
__device__ float g_thr   [BB];
__device__ int   g_nzc   [BB];
__device__ int   g_nzi   [BB*NZCAP];
__device__ int   g_nzj   [BB*NZCAP];

// pre-split weight buffers (bf16 h/r packed pairs, fragment order)
// size = NT * NC * 1024 u32
__device__ uint32_t g_W0h[6*48*1024],  g_W0r[6*48*1024];
__device__ uint32_t g_lch[6*48*1024],  g_lcr[6*48*1024];
__device__ uint32_t g_qwh[4*96*1024],  g_qwr[4*96*1024];
__device__ uint32_t g_kwh[4*96*1024],  g_kwr[4*96*1024];
__device__ uint32_t g_W1h[6*96*1024],  g_W1r[6*96*1024];
__device__ uint32_t g_f1h[6*48*1024],  g_f1r[6*48*1024];
__device__ uint32_t g_f2h[6*48*1024],  g_f2r[6*48*1024];

enum { EP_STORE=0, EP_BIASCOL=1, EP_GCN=3, EP_RELU=4, EP_GCN0=5 };

__device__ __forceinline__ void bfsplit2(float v0, float v1, uint32_t& hw, uint32_t& rw) {
    __nv_bfloat16 h0 = __float2bfloat16_rn(v0);
    __nv_bfloat16 h1 = __float2bfloat16_rn(v1);
    __nv_bfloat16 r0 = __float2bfloat16_rn(v0 - __bfloat162float(h0));
    __nv_bfloat16 r1 = __float2bfloat16_rn(v1 - __bfloat162float(h1));
    hw = (uint32_t)__bfloat16_as_ushort(h0) | ((uint32_t)__bfloat16_as_ushort(h1) << 16);
    rw = (uint32_t)__bfloat16_as_ushort(r0) | ((uint32_t)__bfloat16_as_ushort(r1) << 16);
}

__device__ __forceinline__ void mma16(float* c, const uint32_t* a, const uint32_t* b) {
    asm volatile(
        "mma.sync.aligned.m16n8k16.row.col.f32.bf16.bf16.f32 "
        "{%0,%1,%2,%3}, {%4,%5,%6,%7}, {%8,%9}, {%0,%1,%2,%3};"
        : "+f"(c[0]), "+f"(c[1]), "+f"(c[2]), "+f"(c[3])
        : "r"(a[0]), "r"(a[1]), "r"(a[2]), "r"(a[3]), "r"(b[0]), "r"(b[1]));
}

// ---------------- pre-split kernel (B fragment order, bf16 h/r packed) ----------
// fi = (nt*32 + lane)*2 + reg;  n = nt*8 + (lane>>2); kp = (lane&3) + reg*4; k = 2*kp
__global__ void splitB_k(const float* __restrict__ src, uint32_t* __restrict__ H,
                         uint32_t* __restrict__ R, int N, int K, int ldb, int NT, int NC) {
    int idx = blockIdx.x * 256 + threadIdx.x;
    if (idx >= NT*NC*1024) return;
    int fi = idx & 1023, blk = idx >> 10;
    int c = blk % NC, tn = blk / NC;
    int reg = fi & 1, t1 = fi >> 1;
    int lane = t1 & 31, nt = t1 >> 5;
    int n = tn*128 + nt*8 + (lane >> 2);
    int kp = (lane & 3) + (reg << 2);
    int k = c*16 + 2*kp;
    float v0 = (n < N && k   < K) ? src[(long)n*ldb + k]   : 0.f;
    float v1 = (n < N && k+1 < K) ? src[(long)n*ldb + k+1] : 0.f;
    uint32_t hw, rw; bfsplit2(v0, v1, hw, rw);
    H[idx] = hw; R[idx] = rw;
}

// ======================= bf16x3 tensor GEMM via mma.sync =======================
// C[M,N] = A[M,K]*op(B). Block 128x128, 8 warps (2x4) of 64x32, m16n8k16 bf16.
// Stage (K=16): AH | AR | BH | BR, 1024 u32 each = 16KB; 2 stages = 32KB.
#define SMT_STAGE 4096
#define SMT_TOTAL (2*SMT_STAGE*4)

template<bool TB, bool BPRE, int EPI>
__global__ __launch_bounds__(256, 2)
void tmma_k(const float* __restrict__ A, const float* __restrict__ Bm, float* __restrict__ C,
            int M, int N, int K, int lda, int ldb, int ldc,
            long sAo, long sAi, long sBo, long sBi, long sCo, long sCi, int innerB,
            const float* __restrict__ bias, const float* __restrict__ denom,
            const float* __restrict__ addm, float scale,
            const uint32_t* __restrict__ bph, const uint32_t* __restrict__ bpr)
{
    extern __shared__ uint32_t smu[];

    int tid = threadIdx.x;
    int wid = tid >> 5, lane = tid & 31;
    int wm = wid >> 2, wn = wid & 3;
    int z = blockIdx.z, zo = z / innerB, zi = z % innerB;
    A  += (long)zo*sAo + (long)zi*sAi;
    Bm += (long)zo*sBo + (long)zi*sBi;
    C  += (long)zo*sCo + (long)zi*sCi;
    int bm = blockIdx.y * 128, bn = blockIdx.x * 128;
    int nc = (K + 15) / 16;

    float acc[4][4][4];
    #pragma unroll
    for (int i = 0; i < 4; i++)
        #pragma unroll
        for (int j = 0; j < 4; j++)
            #pragma unroll
            for (int r = 0; r < 4; r++) acc[i][j][r] = 0.f;

    float av0[4], av1[4], bv0[4], bv1[4];
    uint4 pbh, pbr;

    auto loadA = [&](int k0) {
        #pragma unroll
        for (int l = 0; l < 4; l++) {
            int idx = tid + l*256;
            int m = idx >> 3, kp = idx & 7;
            int gr = bm + m, gk = k0 + 2*kp;
            av0[l] = (gr < M && gk   < K) ? A[(long)gr*lda + gk]     : 0.f;
            av1[l] = (gr < M && gk+1 < K) ? A[(long)gr*lda + gk + 1] : 0.f;
        }
    };
    auto loadB = [&](int c) {
        if (BPRE) {
            long blk = ((long)(bn>>7)*nc + c)*1024;
            pbh = ((const uint4*)(bph + blk))[tid];
            pbr = ((const uint4*)(bpr + blk))[tid];
        } else {
            int k0 = c*16;
            #pragma unroll
            for (int l = 0; l < 4; l++) {
                int idx = tid + l*256;
                int n, kp;
                if (TB) { n = idx >> 3;  kp = idx & 7; }     // B[N,K]: k fast -> coalesced pairs
                else    { kp = idx >> 7; n = idx & 127; }    // B[K,N]: n fast -> coalesced
                int gn = bn + n, gk = k0 + 2*kp;
                bool okn = (gn < N);
                bv0[l] = (okn && gk   < K) ? (TB ? Bm[(long)gn*ldb + gk]     : Bm[(long)gk*ldb + gn])     : 0.f;
                bv1[l] = (okn && gk+1 < K) ? (TB ? Bm[(long)gn*ldb + gk + 1] : Bm[(long)(gk+1)*ldb + gn]) : 0.f;
            }
        }
    };
    auto stageA = [&](uint32_t* buf) {
        uint32_t* AH = buf; uint32_t* AR = buf + 1024;
        #pragma unroll
        for (int l = 0; l < 4; l++) {
            int idx = tid + l*256;
            int m = idx >> 3, kp = idx & 7;
            uint32_t hw, rw; bfsplit2(av0[l], av1[l], hw, rw);
            int mt = m >> 4, rr = m & 15;
            int reg = ((rr >> 3) & 1) | ((kp >> 2) << 1);
            int ln = (rr & 7)*4 + (kp & 3);
            int fi = (mt*32 + ln)*4 + reg;
            AH[fi] = hw; AR[fi] = rw;
        }
    };
    auto stageB = [&](uint32_t* buf) {
        if (BPRE) {
            ((uint4*)(buf + 2048))[tid] = pbh;
            ((uint4*)(buf + 3072))[tid] = pbr;
        } else {
            uint32_t* BH = buf + 2048; uint32_t* BR = buf + 3072;
            #pragma unroll
            for (int l = 0; l < 4; l++) {
                int idx = tid + l*256;
                int n, kp;
                if (TB) { n = idx >> 3;  kp = idx & 7; }
                else    { kp = idx >> 7; n = idx & 127; }
                uint32_t hw, rw; bfsplit2(bv0[l], bv1[l], hw, rw);
                int nt = n >> 3, nn = n & 7;
                int reg = (kp >> 2) & 1;
                int ln = nn*4 + (kp & 3);
                int fi = (nt*32 + ln)*2 + reg;
                BH[fi] = hw; BR[fi] = rw;
            }
        }
    };
    auto compute = [&](const uint32_t* buf) {
        const uint32_t* AH = buf;        const uint32_t* AR = buf + 1024;
        const uint32_t* BH = buf + 2048; const uint32_t* BR = buf + 3072;
        uint32_t bh[4][2], br[4][2];
        #pragma unroll
        for (int nt = 0; nt < 4; nt++) {
            int bbase = ((wn*4 + nt)*32 + lane)*2;
            *(uint2*)bh[nt] = *(const uint2*)(BH + bbase);
            *(uint2*)br[nt] = *(const uint2*)(BR + bbase);
        }
        #pragma unroll
        for (int mt = 0; mt < 4; mt++) {
            uint32_t ah[4], ar[4];
            int abase = ((wm*4 + mt)*32 + lane)*4;
            *(uint4*)ah = *(const uint4*)(AH + abase);
            *(uint4*)ar = *(const uint4*)(AR + abase);
            #pragma unroll
            for (int nt = 0; nt < 4; nt++) {
                mma16(acc[mt][nt], ah, bh[nt]);
                mma16(acc[mt][nt], ah, br[nt]);
                mma16(acc[mt][nt], ar, bh[nt]);
            }
        }
    };

    loadA(0); loadB(0);
    for (int c = 0; c < nc; c++) {
        uint32_t* buf = smu + (c & 1) * SMT_STAGE;
        stageA(buf);
        stageB(buf);
        __syncthreads();
        if (c + 1 < nc) { loadA((c+1)*16); loadB(c+1); }
        compute(buf);
    }

    // epilogue (C layout identical to tf32 path)
    int r0 = lane >> 2, c0 = 2*(lane & 3);
    #pragma unroll
    for (int mt = 0; mt < 4; mt++) {
        #pragma unroll
        for (int half = 0; half < 2; half++) {
            int gr = bm + wm*64 + mt*16 + r0 + half*8;
            if (gr >= M) continue;
            float dn = (EPI == EP_GCN) ? denom[gr] : 1.f;
            #pragma unroll
            for (int nt = 0; nt < 4; nt++) {
                #pragma unroll
                for (int e = 0; e < 2; e++) {
                    int gc = bn + wn*32 + nt*8 + c0 + e;
                    if (gc >= N) continue;
                    float v = acc[mt][nt][half*2 + e];
                    if (EPI == EP_STORE)        v *= scale;
                    else if (EPI == EP_BIASCOL) v += bias[gc];
                    else if (EPI == EP_GCN)     v = fmaxf((v + bias[gc]) / dn, 0.f)
                                                  + addm[(long)gr*ldc + gc];
                    else if (EPI == EP_RELU)    v = fmaxf(v, 0.f);
                    else if (EPI == EP_GCN0)    v = v + bias[gc] + fmaxf(bias[gc], 0.f);
                    C[(long)gr*ldc + gc] = v;
                }
            }
        }
    }
}

// ---------------- small kernels ----------------
__global__ void rowsum_adj_k(const float* __restrict__ a, float* __restrict__ d) {
    int row = blockIdx.x;
    const float* p = a + (long)row * NN;
    float s = 0.f;
    for (int j = threadIdx.x; j < NN; j += 128) s += p[j];
    __shared__ float sm[128];
    sm[threadIdx.x] = s; __syncthreads();
    for (int o = 64; o > 0; o >>= 1) { if (threadIdx.x < o) sm[threadIdx.x] += sm[threadIdx.x+o]; __syncthreads(); }
    if (threadIdx.x == 0) d[row] = sm[0] + 1.f;
}

__global__ void copy_inputs_k(const float* __restrict__ in, float* __restrict__ x) {
    long i = (long)blockIdx.x * 256 + threadIdx.x;
    if (i < (long)MTOT * DD) {
        long r = i / DD, c = i % DD;
        x[r * DHD + c] = in[i];
    }
}

__global__ void wpack_k(const float* __restrict__ cvw, float* __restrict__ wp) {
    int i = blockIdx.x * 256 + threadIdx.x;
    if (i < 3*NN*NN) {
        int t = i / (NN*NN);
        int o = (i / NN) % NN;
        int c = i % NN;
        wp[i] = cvw[(long)o*NN*3 + c*3 + t];
    }
}

__global__ void combine_k(const float* __restrict__ Y, const float* __restrict__ cvb,
                          float* __restrict__ conve) {
    long i = (long)blockIdx.x * 256 + threadIdx.x;
    if (i < (long)BB*NN*LCV) {
        int  l = (int)(i % LCV);
        int  o = (int)((i / LCV) % NN);
        int  b = (int)(i / ((long)NN*LCV));
        long base = ((long)b*NN + o)*DD + l;
        const long ts = (long)BB*NN*DD;
        float v = Y[base] + Y[ts + base + 1] + Y[2*ts + base + 2];
        conve[i] = fmaxf(v + cvb[o], 0.f);
    }
}

__global__ __launch_bounds__(128) void softmax_k(float* __restrict__ P) {
    int row = blockIdx.x;
    float* p = P + (long)row * NN;
    int t = threadIdx.x;
    __shared__ float sm[128];
    float m = -1e30f;
    for (int j = t; j < NKEY; j += 128) m = fmaxf(m, p[j]);
    sm[t] = m; __syncthreads();
    for (int o = 64; o > 0; o >>= 1) { if (t < o) sm[t] = fmaxf(sm[t], sm[t+o]); __syncthreads(); }
    float M = sm[0]; __syncthreads();
    float s = 0.f;
    for (int j = t; j < NKEY; j += 128) { float e = expf(p[j] - M); p[j] = e; s += e; }
    sm[t] = s; __syncthreads();
    for (int o = 64; o > 0; o >>= 1) { if (t < o) sm[t] += sm[t+o]; __syncthreads(); }
    float S = sm[0]; __syncthreads();
    for (int j = t; j < NKEY; j += 128) p[j] = p[j] / S;
    for (int j = NKEY + t; j < NN; j += 128) p[j] = 0.f;
}

__global__ __launch_bounds__(256) void top2_k(const float* __restrict__ P,
                                              float* __restrict__ thr) {
    int b = blockIdx.x;
    const float* p = P + (long)b * NN * NN;
    float m1 = -1e30f, m2 = -1e30f;
    for (long i = threadIdx.x; i < (long)NN*NN; i += 256) {
        float v = p[i];
        if (v > m1) { m2 = m1; m1 = v; }
        else if (v > m2) m2 = v;
    }
    __shared__ float s1[256], s2[256];
    s1[threadIdx.x] = m1; s2[threadIdx.x] = m2; __syncthreads();
    if (threadIdx.x == 0) {
        float M1 = -1e30f, M2 = -1e30f;
        for (int i = 0; i < 256; i++) {
            float a = s1[i], a2 = s2[i];
            if (a > M1) { M2 = fmaxf(M1, a2); M1 = a; }
            else if (a > M2) M2 = a;
        }
        thr[b] = M2;
    }
}

__global__ __launch_bounds__(256) void extract_k(const float* __restrict__ P,
                                                 const float* __restrict__ thr,
                                                 int* __restrict__ nzc,
                                                 int* __restrict__ nzi,
                                                 int* __restrict__ nzj) {
    int b = blockIdx.x;
    const float* p = P + (long)b * NN * NN;
    float th = thr[b];
    __shared__ int cnt;
    __shared__ int li[NZCAP], lj[NZCAP];
    if (threadIdx.x == 0) cnt = 0;
    __syncthreads();
    for (long idx = threadIdx.x; idx < (long)NN*NN; idx += 256) {
        if (p[idx] >= th) {
            int s = atomicAdd(&cnt, 1);
            if (s < NZCAP) { li[s] = (int)(idx / NN); lj[s] = (int)(idx % NN); }
        }
    }
    __syncthreads();
    if (threadIdx.x == 0) {
        int n = cnt < NZCAP ? cnt : NZCAP;
        for (int a = 1; a < n; a++) {
            int ii = li[a], jj = lj[a];
            int w = a - 1;
            while (w >= 0 && (li[w] > ii || (li[w] == ii && lj[w] > jj))) {
                li[w+1] = li[w]; lj[w+1] = lj[w]; w--;
            }
            li[w+1] = ii; lj[w+1] = jj;
        }
        nzc[b] = n;
        for (int a = 0; a < n; a++) { nzi[b*NZCAP + a] = li[a]; nzj[b*NZCAP + a] = lj[a]; }
    }
}

__global__ __launch_bounds__(256) void fixup_k(const int* __restrict__ nzc,
                                               const int* __restrict__ nzi,
                                               const int* __restrict__ nzj,
                                               const float* __restrict__ x,
                                               const float* __restrict__ W1w,
                                               const float* __restrict__ W1b,
                                               float* __restrict__ out2) {
    int b = blockIdx.x, t = threadIdx.x;
    int n = nzc[b];
    __shared__ int ei[NZCAP], ej[NZCAP];
    __shared__ float axrow[DHD];
    if (t < n) { ei[t] = nzi[b*NZCAP + t]; ej[t] = nzj[b*NZCAP + t]; }
    __syncthreads();
    for (int e = 0; e < n; e++) {
        int i = ei[e];
        bool first = true;
        for (int e2 = 0; e2 < e; e2++) if (ei[e2] == i) first = false;
        if (!first) continue;
        for (int k = t; k < DHD; k += 256) axrow[k] = 0.f;
        __syncthreads();
        float den = 1.f;
        for (int e2 = e; e2 < n; e2++) {
            if (ei[e2] != i) continue;
            int j = ej[e2];
            float bji = 0.f;
            for (int e3 = 0; e3 < n; e3++) if (ei[e3] == j && ej[e3] == i) bji = 1.f;
            float a = (i == j) ? 1.f : (1.f + bji);
            den += a;
            const float* xr = x + ((long)b*NN + j)*DHD;
            for (int k = t; k < DHD; k += 256) axrow[k] += a * xr[k];
            __syncthreads();
        }
        float* orow = out2 + ((long)b*NN + i)*DD;
        for (int c = t; c < DD; c += 256) {
            const float* wrow = W1w + (long)c*DHD;
            float dot = 0.f;
            for (int k = 0; k < DHD; k++) dot += axrow[k] * wrow[k];
            float bc = W1b[c];
            float xw1v = orow[c] - fmaxf(bc, 0.f);
            orow[c] = fmaxf((dot + bc) / den, 0.f) + xw1v;
        }
        __syncthreads();
    }
}

// ---------------- launch ----------------
static inline dim3 ggrid(int Ncols, int Mrows, int batch) {
    return dim3((Ncols + 127) / 128, (Mrows + 127) / 128, batch);
}

extern "C" void kernel_launch(void* const* d_in, const int* in_sizes, int n_in,
                              void* d_out, int out_size) {
    const float* adj    = (const float*)d_in[0];
    const float* inputs = (const float*)d_in[1];
    const float* W0w = (const float*)d_in[3];  const float* W0b = (const float*)d_in[4];
    const float* W1w = (const float*)d_in[5];  const float* W1b = (const float*)d_in[6];
    const float* cvw = (const float*)d_in[7];  const float* cvb = (const float*)d_in[8];
    const float* lcw = (const float*)d_in[9];  const float* lcb = (const float*)d_in[10];
    const float* f1w = (const float*)d_in[11]; const float* f2w = (const float*)d_in[12];
    const float* qw  = (const float*)d_in[13]; const float* qb  = (const float*)d_in[14];
    const float* kw  = (const float*)d_in[15]; const float* kb  = (const float*)d_in[16];
    float* out = (float*)d_out;

    float *p_denom, *p_Ax, *p_xw0, *p_out1, *p_wp, *p_Y, *p_conve, *p_x, *p_q, *p_k, *p_P;
    float *p_out2, *p_h1, *p_thr;
    int *p_nzc, *p_nzi, *p_nzj;
    uint32_t *W0h,*W0r,*lch,*lcr,*qwh,*qwr,*kwh,*kwr,*W1h,*W1r,*f1h,*f1r,*f2h,*f2r;
    cudaGetSymbolAddress((void**)&p_denom,  g_denom);
    cudaGetSymbolAddress((void**)&p_Ax,     g_Ax);
    cudaGetSymbolAddress((void**)&p_xw0,    g_xw0);
    cudaGetSymbolAddress((void**)&p_out1,   g_out1);
    cudaGetSymbolAddress((void**)&p_wp,     g_wpack);
    cudaGetSymbolAddress((void**)&p_Y,      g_Y);
    cudaGetSymbolAddress((void**)&p_conve,  g_conve);
    cudaGetSymbolAddress((void**)&p_x,      g_x);
    cudaGetSymbolAddress((void**)&p_q,      g_q);
    cudaGetSymbolAddress((void**)&p_k,      g_k);
    cudaGetSymbolAddress((void**)&p_P,      g_P);
    cudaGetSymbolAddress((void**)&p_out2,   g_out2);
    cudaGetSymbolAddress((void**)&p_h1,     g_h1);
    cudaGetSymbolAddress((void**)&p_thr,    g_thr);
    cudaGetSymbolAddress((void**)&p_nzc,    g_nzc);
    cudaGetSymbolAddress((void**)&p_nzi,    g_nzi);
    cudaGetSymbolAddress((void**)&p_nzj,    g_nzj);
    cudaGetSymbolAddress((void**)&W0h, g_W0h);  cudaGetSymbolAddress((void**)&W0r, g_W0r);
    cudaGetSymbolAddress((void**)&lch, g_lch);  cudaGetSymbolAddress((void**)&lcr, g_lcr);
    cudaGetSymbolAddress((void**)&qwh, g_qwh);  cudaGetSymbolAddress((void**)&qwr, g_qwr);
    cudaGetSymbolAddress((void**)&kwh, g_kwh);  cudaGetSymbolAddress((void**)&kwr, g_kwr);
    cudaGetSymbolAddress((void**)&W1h, g_W1h);  cudaGetSymbolAddress((void**)&W1r, g_W1r);
    cudaGetSymbolAddress((void**)&f1h, g_f1h);  cudaGetSymbolAddress((void**)&f1r, g_f1r);
    cudaGetSymbolAddress((void**)&f2h, g_f2h);  cudaGetSymbolAddress((void**)&f2r, g_f2r);

    #define SETSM(F) cudaFuncSetAttribute(F, cudaFuncAttributeMaxDynamicSharedMemorySize, SMT_TOTAL)
    SETSM((tmma_k<false, false, EP_STORE>));
    SETSM((tmma_k<true,  false, EP_STORE>));
    SETSM((tmma_k<true,  true,  EP_STORE>));
    SETSM((tmma_k<true,  true,  EP_BIASCOL>));
    SETSM((tmma_k<true,  true,  EP_GCN>));
    SETSM((tmma_k<true,  true,  EP_RELU>));
    SETSM((tmma_k<true,  true,  EP_GCN0>));

    const long NND = (long)NN*DD, NNN = (long)NN*NN, NNH = (long)NN*DHD;
    const uint32_t* NU = nullptr;

    // 0) pre-split weights (bf16 h/r, fragment order)
    splitB_k<<<(6*48*1024)/256, 256>>>(W0w, W0h, W0r, DD, DD, DD, 6, 48);
    splitB_k<<<(6*48*1024)/256, 256>>>(lcw, lch, lcr, DD, LCV, LCV, 6, 48);
    splitB_k<<<(4*96*1024)/256, 256>>>(qw,  qwh, qwr, DKH, DHD, DHD, 4, 96);
    splitB_k<<<(4*96*1024)/256, 256>>>(kw,  kwh, kwr, DKH, DHD, DHD, 4, 96);
    splitB_k<<<(6*96*1024)/256, 256>>>(W1w, W1h, W1r, DD, DHD, DHD, 6, 96);
    splitB_k<<<(6*48*1024)/256, 256>>>(f1w, f1h, f1r, DD, DD, DD, 6, 48);
    splitB_k<<<(6*48*1024)/256, 256>>>(f2w, f2h, f2r, DD, DD, DD, 6, 48);

    // 1) denom
    rowsum_adj_k<<<MTOT, 128>>>(adj, p_denom);

    // 2) Ax = adj @ inputs
    tmma_k<false, false, EP_STORE><<<ggrid(DD, NN, BB), 256, SMT_TOTAL>>>(
        adj, inputs, p_Ax, NN, DD, NN, NN, DD, DD,
        NNN, 0, NND, 0, NND, 0, 1, nullptr, nullptr, nullptr, 1.f, NU, NU);

    // 3) xw0 = inputs @ W0^T + b   [B pre-split]
    tmma_k<true, true, EP_BIASCOL><<<ggrid(DD, MTOT, 1), 256, SMT_TOTAL>>>(
        inputs, W0w, p_xw0, MTOT, DD, DD, DD, DD, DD,
        0,0,0,0,0,0, 1, W0b, nullptr, nullptr, 1.f, W0h, W0r);

    // 4) out1 = relu((Ax@W0^T + b)/denom) + xw0   [B pre-split]
    tmma_k<true, true, EP_GCN><<<ggrid(DD, MTOT, 1), 256, SMT_TOTAL>>>(
        p_Ax, W0w, p_out1, MTOT, DD, DD, DD, DD, DD,
        0,0,0,0,0,0, 1, W0b, p_denom, p_xw0, 1.f, W0h, W0r);

    // 5a) conv weight repack
    wpack_k<<<(3*NN*NN + 255)/256, 256>>>(cvw, p_wp);
    // 5b) Y[t][b] = W_t @ out1[b]  (batched 48)
    tmma_k<false, false, EP_STORE><<<ggrid(DD, NN, 3*BB), 256, SMT_TOTAL>>>(
        p_wp, p_out1, p_Y, NN, DD, NN, NN, DD, DD,
        NNN, 0, 0, NND, (long)BB*NN*DD, NND, BB,
        nullptr, nullptr, nullptr, 1.f, NU, NU);
    // 5c) combine + relu + bias
    combine_k<<<(int)(((long)BB*NN*LCV + 255)/256), 256>>>(p_Y, cvb, p_conve);

    // 7) x[:, :768] = inputs
    copy_inputs_k<<<(int)(((long)MTOT*DD + 255)/256), 256>>>(inputs, p_x);

    // 8) x[:, 768:] = conve @ linearc^T + b   [B pre-split]
    tmma_k<true, true, EP_BIASCOL><<<ggrid(DD, MTOT, 1), 256, SMT_TOTAL>>>(
        p_conve, lcw, p_x + DD, MTOT, DD, LCV, LCV, LCV, DHD,
        0,0,0,0,0,0, 1, lcb, nullptr, nullptr, 1.f, lch, lcr);

    // 9) q projection (head 0)   [B pre-split]
    tmma_k<true, true, EP_BIASCOL><<<ggrid(DKH, MTOT, 1), 256, SMT_TOTAL>>>(
        p_x, qw, p_q, MTOT, DKH, DHD, DHD, DHD, DKH,
        0,0,0,0,0,0, 1, qb, nullptr, nullptr, 1.f, qwh, qwr);
    // 10) k projection (head 0, keys<384, batched)   [B pre-split]
    tmma_k<true, true, EP_BIASCOL><<<ggrid(DKH, NKEY, BB), 256, SMT_TOTAL>>>(
        p_x, kw, p_k, NKEY, DKH, DHD, DHD, DHD, DKH,
        NNH, 0, 0, 0, (long)NKEY*DKH, 0, 1, kb, nullptr, nullptr, 1.f, kwh, kwr);

    // 11) scores = q k^T / sqrt(512) (batched 16)
    {
        float scl = 1.0f / sqrtf(512.0f);
        tmma_k<true, false, EP_STORE><<<ggrid(NKEY, NN, BB), 256, SMT_TOTAL>>>(
            p_q, p_k, p_P, NN, NKEY, DKH, DKH, DKH, NN,
            (long)NN*DKH, 0, (long)NKEY*DKH, 0, NNN, 0, 1,
            nullptr, nullptr, nullptr, scl, NU, NU);
    }

    // 12) softmax (head 0)
    softmax_k<<<BB*NN, 128>>>(p_P);
    // 14) top-2 threshold
    top2_k<<<BB, 256>>>(p_P, p_thr);
    // 15) sparse bbin extraction
    extract_k<<<BB, 256>>>(p_P, p_thr, p_nzc, p_nzi, p_nzj);

    // 17) out2 = relu(b) + (x @ W1^T + b)   [B pre-split]
    tmma_k<true, true, EP_GCN0><<<ggrid(DD, MTOT, 1), 256, SMT_TOTAL>>>(
        p_x, W1w, p_out2, MTOT, DD, DHD, DHD, DHD, DD,
        0,0,0,0,0,0, 1, W1b, nullptr, nullptr, 1.f, W1h, W1r);

    // 18) sparse fixup
    fixup_k<<<BB, 256>>>(p_nzc, p_nzi, p_nzj, p_x, W1w, W1b, p_out2);

    // 19) h1 = relu(out2 @ fc1^T)   [B pre-split]
    tmma_k<true, true, EP_RELU><<<ggrid(DD, MTOT, 1), 256, SMT_TOTAL>>>(
        p_out2, f1w, p_h1, MTOT, DD, DD, DD, DD, DD,
        0,0,0,0,0,0, 1, nullptr, nullptr, nullptr, 1.f, f1h, f1r);

    // 20) out = h1 @ fc2^T   [B pre-split]
    tmma_k<true, true, EP_STORE><<<ggrid(DD, MTOT, 1), 256, SMT_TOTAL>>>(
        p_h1, f2w, out, MTOT, DD, DD, DD, DD, DD,
        0,0,0,0,0,0, 1, nullptr, nullptr, nullptr, 1.f, f2h, f2r);
}